// round 1
// baseline (speedup 1.0000x reference)
#include <cuda_runtime.h>
#include <math.h>

#define NB 8
#define SS 2048
#define HH 1024
#define MM 1024   // S/2

// db2 filter taps (fp32)
#define C_H0 0.48296291314469025f
#define C_H1 0.83651630373780790f
#define C_H2 0.22414386804185735f
#define C_H3 (-0.12940952255092145f)

// ---- scratch (static device globals; no allocation in kernel_launch) ----
__device__ __align__(16) float g_ca[NB * MM * HH];
__device__ __align__(16) float g_cd[NB * MM * HH];
__device__ __align__(16) float g_pa[NB * MM * HH];
__device__ __align__(16) float g_pd[NB * MM * HH];
__device__ __align__(16) float g_recon[NB * SS * HH];
__device__ __align__(16) float g_wA[3 * HH * HH];  // [k][h][o]
__device__ __align__(16) float g_wD[3 * HH * HH];  // [k][h][o]
__device__ __align__(16) float g_wO[HH * HH];      // [h][o]

__device__ __forceinline__ float gelu_exact(float v) {
    return 0.5f * v * (1.0f + erff(v * 0.70710678118654752f));
}

// ---------------------------------------------------------------------------
// Weight prep: transpose conv weights [o,h,3] -> [3][h][o]
// ---------------------------------------------------------------------------
__global__ void transpose_conv_w(const float* __restrict__ w, int which) {
    float* outw = which ? g_wD : g_wA;
    __shared__ float t[3][32][33];
    int obase = blockIdx.y << 5;
    int hbase = blockIdx.x << 5;
    int tx = threadIdx.x, ty0 = threadIdx.y;
#pragma unroll
    for (int i = 0; i < 32; i += 8) {
        int o = obase + ty0 + i;
        int h = hbase + tx;
        const float* p = w + ((size_t)o * HH + h) * 3;
        t[0][ty0 + i][tx] = p[0];
        t[1][ty0 + i][tx] = p[1];
        t[2][ty0 + i][tx] = p[2];
    }
    __syncthreads();
#pragma unroll
    for (int k = 0; k < 3; k++) {
#pragma unroll
        for (int i = 0; i < 32; i += 8) {
            int h = hbase + ty0 + i;
            int o = obase + tx;
            outw[(size_t)k * HH * HH + (size_t)h * HH + o] = t[k][tx][ty0 + i];
        }
    }
}

// transpose w_out [o,h] -> [h][o]
__global__ void transpose_wo(const float* __restrict__ w) {
    __shared__ float t[32][33];
    int obase = blockIdx.y << 5;
    int hbase = blockIdx.x << 5;
    int tx = threadIdx.x, ty0 = threadIdx.y;
#pragma unroll
    for (int i = 0; i < 32; i += 8) {
        int o = obase + ty0 + i;
        int h = hbase + tx;
        t[ty0 + i][tx] = w[(size_t)o * HH + h];
    }
    __syncthreads();
#pragma unroll
    for (int i = 0; i < 32; i += 8) {
        int h = hbase + ty0 + i;
        int o = obase + tx;
        g_wO[(size_t)h * HH + o] = t[tx][ty0 + i];
    }
}

// ---------------------------------------------------------------------------
// DWT (db2, symmetric): ca[m] = h0*x[2m-2]+h1*x[2m-1]+h2*x[2m]+h3*x[2m+1]
//                       cd[m] = h3*x[2m-2]-h2*x[2m-1]+h1*x[2m]-h0*x[2m+1]
// left reflection: s=-1 -> x[0], s=-2 -> x[1]. (right edge never reached, m<1024)
// ---------------------------------------------------------------------------
__global__ void dwt_kernel(const float* __restrict__ x) {
    int bm = blockIdx.x;
    int b = bm >> 10, m = bm & 1023;
    int h = threadIdx.x << 2;
    int s0 = 2 * m - 2, s1 = 2 * m - 1;
    if (s0 < 0) s0 = -s0 - 1;
    if (s1 < 0) s1 = -s1 - 1;
    const float* xb = x + (size_t)b * SS * HH + h;
    float4 v0 = *(const float4*)(xb + (size_t)s0 * HH);
    float4 v1 = *(const float4*)(xb + (size_t)s1 * HH);
    float4 v2 = *(const float4*)(xb + (size_t)(2 * m) * HH);
    float4 v3 = *(const float4*)(xb + (size_t)(2 * m + 1) * HH);
    float4 ca, cd;
    ca.x = C_H0 * v0.x + C_H1 * v1.x + C_H2 * v2.x + C_H3 * v3.x;
    ca.y = C_H0 * v0.y + C_H1 * v1.y + C_H2 * v2.y + C_H3 * v3.y;
    ca.z = C_H0 * v0.z + C_H1 * v1.z + C_H2 * v2.z + C_H3 * v3.z;
    ca.w = C_H0 * v0.w + C_H1 * v1.w + C_H2 * v2.w + C_H3 * v3.w;
    cd.x = C_H3 * v0.x - C_H2 * v1.x + C_H1 * v2.x - C_H0 * v3.x;
    cd.y = C_H3 * v0.y - C_H2 * v1.y + C_H1 * v2.y - C_H0 * v3.y;
    cd.z = C_H3 * v0.z - C_H2 * v1.z + C_H1 * v2.z - C_H0 * v3.z;
    cd.w = C_H3 * v0.w - C_H2 * v1.w + C_H1 * v2.w - C_H0 * v3.w;
    size_t off = ((size_t)b * MM + m) * HH + h;
    *(float4*)(g_ca + off) = ca;
    *(float4*)(g_cd + off) = cd;
}

// ---------------------------------------------------------------------------
// Conv3(H->H) + GELU as implicit GEMM.
// C[r=(b,m), o] = gelu( bias[o] + sum_{delta,h} A[b, m+delta-1, h] * W[delta][h][o] )
// BM=BN=128, BK=8, 256 threads, 8x8 per thread.
// ---------------------------------------------------------------------------
__global__ __launch_bounds__(256) void conv_gelu_gemm(
    const float* __restrict__ bias_a, const float* __restrict__ bias_d) {
    const float* A = blockIdx.z ? g_cd : g_ca;
    const float* Bw = blockIdx.z ? g_wD : g_wA;
    const float* bias = blockIdx.z ? bias_d : bias_a;
    float* C = blockIdx.z ? g_pd : g_pa;

    __shared__ __align__(16) float As[8][128];
    __shared__ __align__(16) float Bs[8][128];

    int tid = threadIdx.x;
    int row0 = blockIdx.y << 7;
    int col0 = blockIdx.x << 7;

    int arow = tid >> 1;
    int acol = (tid & 1) << 2;
    int r = row0 + arow;
    int ab = r >> 10, am = r & 1023;

    int bk = tid >> 5;
    int bo = (tid & 31) << 2;

    int ty = tid >> 4, tx = tid & 15;

    float acc[8][8];
#pragma unroll
    for (int i = 0; i < 8; i++)
#pragma unroll
        for (int j = 0; j < 8; j++) acc[i][j] = 0.0f;

    for (int t = 0; t < 384; t++) {
        int kk = t << 3;
        int delta = kk >> 10;
        int hh = kk & 1023;

        float4 av = make_float4(0.f, 0.f, 0.f, 0.f);
        int msrc = am + delta - 1;
        if (msrc >= 0 && msrc < MM)
            av = *(const float4*)(A + ((size_t)ab * MM + msrc) * HH + hh + acol);
        As[acol + 0][arow] = av.x;
        As[acol + 1][arow] = av.y;
        As[acol + 2][arow] = av.z;
        As[acol + 3][arow] = av.w;

        float4 bv = *(const float4*)(Bw + ((size_t)delta * HH + (hh + bk)) * HH + col0 + bo);
        *(float4*)(&Bs[bk][bo]) = bv;

        __syncthreads();
#pragma unroll
        for (int k = 0; k < 8; k++) {
            float a[8], bb[8];
            *(float4*)(a) = *(const float4*)(&As[k][ty * 8]);
            *(float4*)(a + 4) = *(const float4*)(&As[k][ty * 8 + 4]);
            *(float4*)(bb) = *(const float4*)(&Bs[k][tx * 8]);
            *(float4*)(bb + 4) = *(const float4*)(&Bs[k][tx * 8 + 4]);
#pragma unroll
            for (int i = 0; i < 8; i++)
#pragma unroll
                for (int j = 0; j < 8; j++)
                    acc[i][j] = fmaf(a[i], bb[j], acc[i][j]);
        }
        __syncthreads();
    }

#pragma unroll
    for (int i = 0; i < 8; i++) {
        int rr = row0 + ty * 8 + i;
        int ob = rr >> 10, om = rr & 1023;
        float* cp = C + ((size_t)ob * MM + om) * HH + col0 + tx * 8;
        float4 o0, o1;
        o0.x = gelu_exact(acc[i][0] + bias[col0 + tx * 8 + 0]);
        o0.y = gelu_exact(acc[i][1] + bias[col0 + tx * 8 + 1]);
        o0.z = gelu_exact(acc[i][2] + bias[col0 + tx * 8 + 2]);
        o0.w = gelu_exact(acc[i][3] + bias[col0 + tx * 8 + 3]);
        o1.x = gelu_exact(acc[i][4] + bias[col0 + tx * 8 + 4]);
        o1.y = gelu_exact(acc[i][5] + bias[col0 + tx * 8 + 5]);
        o1.z = gelu_exact(acc[i][6] + bias[col0 + tx * 8 + 6]);
        o1.w = gelu_exact(acc[i][7] + bias[col0 + tx * 8 + 7]);
        *(float4*)(cp) = o0;
        *(float4*)(cp + 4) = o1;
    }
}

// ---------------------------------------------------------------------------
// iDWT: recon length 2046 per batch, rows 2046..2047 zero.
//  n even: h0*pa[n/2+1] + h2*pa[n/2] + h3*pd[n/2+1] + h1*pd[n/2]
//  n odd : h1*pa[(n+1)/2] + h3*pa[(n-1)/2] - h2*pd[(n+1)/2] - h0*pd[(n-1)/2]
// ---------------------------------------------------------------------------
__global__ void idwt_kernel() {
    int bn = blockIdx.x;
    int b = bn >> 11, n = bn & 2047;
    int h = threadIdx.x << 2;
    size_t outoff = ((size_t)b * SS + n) * HH + h;
    if (n >= 2046) {
        *(float4*)(g_recon + outoff) = make_float4(0.f, 0.f, 0.f, 0.f);
        return;
    }
    int m0, m1;
    float wa0, wa1, wd0, wd1;
    if (!(n & 1)) {
        m0 = n >> 1; m1 = m0 + 1;
        wa1 = C_H0; wa0 = C_H2; wd1 = C_H3; wd0 = C_H1;
    } else {
        m0 = (n - 1) >> 1; m1 = m0 + 1;
        wa1 = C_H1; wa0 = C_H3; wd1 = -C_H2; wd0 = -C_H0;
    }
    size_t base = (size_t)b * MM * HH + h;
    float4 pa0 = *(const float4*)(g_pa + base + (size_t)m0 * HH);
    float4 pa1 = *(const float4*)(g_pa + base + (size_t)m1 * HH);
    float4 pd0 = *(const float4*)(g_pd + base + (size_t)m0 * HH);
    float4 pd1 = *(const float4*)(g_pd + base + (size_t)m1 * HH);
    float4 rv;
    rv.x = wa0 * pa0.x + wa1 * pa1.x + wd0 * pd0.x + wd1 * pd1.x;
    rv.y = wa0 * pa0.y + wa1 * pa1.y + wd0 * pd0.y + wd1 * pd1.y;
    rv.z = wa0 * pa0.z + wa1 * pa1.z + wd0 * pd0.z + wd1 * pd1.z;
    rv.w = wa0 * pa0.w + wa1 * pa1.w + wd0 * pd0.w + wd1 * pd1.w;
    *(float4*)(g_recon + outoff) = rv;
}

// ---------------------------------------------------------------------------
// Output GEMM: out[r=(b,s), o] = sum_h recon[r,h] * wO[h][o] + b_out[o]
// ---------------------------------------------------------------------------
__global__ __launch_bounds__(256) void out_gemm(const float* __restrict__ b_out,
                                                float* __restrict__ out) {
    __shared__ __align__(16) float As[8][128];
    __shared__ __align__(16) float Bs[8][128];

    int tid = threadIdx.x;
    int row0 = blockIdx.y << 7;
    int col0 = blockIdx.x << 7;

    int arow = tid >> 1;
    int acol = (tid & 1) << 2;
    int r = row0 + arow;

    int bk = tid >> 5;
    int bo = (tid & 31) << 2;

    int ty = tid >> 4, tx = tid & 15;

    float acc[8][8];
#pragma unroll
    for (int i = 0; i < 8; i++)
#pragma unroll
        for (int j = 0; j < 8; j++) acc[i][j] = 0.0f;

    for (int t = 0; t < 128; t++) {
        int hh = t << 3;
        float4 av = *(const float4*)(g_recon + (size_t)r * HH + hh + acol);
        As[acol + 0][arow] = av.x;
        As[acol + 1][arow] = av.y;
        As[acol + 2][arow] = av.z;
        As[acol + 3][arow] = av.w;

        float4 bv = *(const float4*)(g_wO + (size_t)(hh + bk) * HH + col0 + bo);
        *(float4*)(&Bs[bk][bo]) = bv;

        __syncthreads();
#pragma unroll
        for (int k = 0; k < 8; k++) {
            float a[8], bb[8];
            *(float4*)(a) = *(const float4*)(&As[k][ty * 8]);
            *(float4*)(a + 4) = *(const float4*)(&As[k][ty * 8 + 4]);
            *(float4*)(bb) = *(const float4*)(&Bs[k][tx * 8]);
            *(float4*)(bb + 4) = *(const float4*)(&Bs[k][tx * 8 + 4]);
#pragma unroll
            for (int i = 0; i < 8; i++)
#pragma unroll
                for (int j = 0; j < 8; j++)
                    acc[i][j] = fmaf(a[i], bb[j], acc[i][j]);
        }
        __syncthreads();
    }

#pragma unroll
    for (int i = 0; i < 8; i++) {
        int rr = row0 + ty * 8 + i;
        float* cp = out + (size_t)rr * HH + col0 + tx * 8;
        float4 o0, o1;
        o0.x = acc[i][0] + b_out[col0 + tx * 8 + 0];
        o0.y = acc[i][1] + b_out[col0 + tx * 8 + 1];
        o0.z = acc[i][2] + b_out[col0 + tx * 8 + 2];
        o0.w = acc[i][3] + b_out[col0 + tx * 8 + 3];
        o1.x = acc[i][4] + b_out[col0 + tx * 8 + 4];
        o1.y = acc[i][5] + b_out[col0 + tx * 8 + 5];
        o1.z = acc[i][6] + b_out[col0 + tx * 8 + 6];
        o1.w = acc[i][7] + b_out[col0 + tx * 8 + 7];
        *(float4*)(cp) = o0;
        *(float4*)(cp + 4) = o1;
    }
}

// ---------------------------------------------------------------------------
extern "C" void kernel_launch(void* const* d_in, const int* in_sizes, int n_in,
                              void* d_out, int out_size) {
    const float* x        = (const float*)d_in[0];
    const float* w_approx = (const float*)d_in[1];
    const float* b_approx = (const float*)d_in[2];
    const float* w_detail = (const float*)d_in[3];
    const float* b_detail = (const float*)d_in[4];
    const float* w_out    = (const float*)d_in[5];
    const float* b_out    = (const float*)d_in[6];
    float* out = (float*)d_out;

    dim3 tb(32, 8);
    dim3 tg(32, 32);
    transpose_conv_w<<<tg, tb>>>(w_approx, 0);
    transpose_conv_w<<<tg, tb>>>(w_detail, 1);
    transpose_wo<<<tg, tb>>>(w_out);

    dwt_kernel<<<NB * MM, 256>>>(x);

    conv_gelu_gemm<<<dim3(HH / 128, NB * MM / 128, 2), 256>>>(b_approx, b_detail);

    idwt_kernel<<<NB * SS, 256>>>();

    out_gemm<<<dim3(HH / 128, NB * SS / 128), 256>>>(b_out, out);
}

// round 3
// speedup vs baseline: 4.9053x; 4.9053x over previous
#include <cuda_runtime.h>
#include <cuda_fp16.h>
#include <math.h>
#include <stdint.h>

#define NB 8
#define SS 2048
#define HH 1024
#define MM 1024
#define MP 1026   // padded rows per batch (zero row below m=0 and above m=1023)

#define C_H0 0.48296291314469025f
#define C_H1 0.83651630373780790f
#define C_H2 0.22414386804185735f
#define C_H3 (-0.12940952255092145f)

// GEMM tiling
#define BM 128
#define BN 128
#define BK 32
#define STAGES 3
#define ROWB 80              // bytes per SMEM tile row (32 halves + 8 pad)
#define TILEB (128 * ROWB)   // 10240 bytes per operand tile
#define STAGEB (2 * TILEB)   // A + B per stage
#define SMEM_BYTES (STAGES * STAGEB)

// ---------------- device scratch ----------------
__device__ __align__(16) __half g_ca[NB * MP * HH];
__device__ __align__(16) __half g_cd[NB * MP * HH];
__device__ __align__(16) float  g_pa[NB * MM * HH];
__device__ __align__(16) float  g_pd[NB * MM * HH];
__device__ __align__(16) __half g_rec[NB * SS * HH];
__device__ __align__(16) __half g_wc[2 * HH * 3072];  // [which][o][delta*1024+h]
__device__ __align__(16) __half g_wo[HH * HH];        // [o][h]

// ---------------- helpers ----------------
__device__ __forceinline__ uint32_t smem_u32(const void* p) {
    uint32_t a;
    asm("{ .reg .u64 t; cvta.to.shared.u64 t, %1; cvt.u32.u64 %0, t; }" : "=r"(a) : "l"(p));
    return a;
}

__device__ __forceinline__ void cp16(uint32_t dst, const void* src) {
    asm volatile("cp.async.cg.shared.global [%0], [%1], 16;" :: "r"(dst), "l"(src));
}

__device__ __forceinline__ void ldm_x4(uint32_t& r0, uint32_t& r1, uint32_t& r2, uint32_t& r3,
                                       uint32_t addr) {
    asm volatile("ldmatrix.sync.aligned.m8n8.x4.shared.b16 {%0,%1,%2,%3}, [%4];"
                 : "=r"(r0), "=r"(r1), "=r"(r2), "=r"(r3) : "r"(addr));
}

__device__ __forceinline__ void mma16816(float* d, const uint32_t* a, const uint32_t* b) {
    asm volatile(
        "mma.sync.aligned.m16n8k16.row.col.f32.f16.f16.f32 "
        "{%0,%1,%2,%3}, {%4,%5,%6,%7}, {%8,%9}, {%0,%1,%2,%3};"
        : "+f"(d[0]), "+f"(d[1]), "+f"(d[2]), "+f"(d[3])
        : "r"(a[0]), "r"(a[1]), "r"(a[2]), "r"(a[3]), "r"(b[0]), "r"(b[1]));
}

__device__ __forceinline__ float gelu_exact(float v) {
    return 0.5f * v * (1.0f + erff(v * 0.70710678118654752f));
}

// ---------------- weight prep ----------------
__global__ void prep_conv_w(const float* __restrict__ wA, const float* __restrict__ wD) {
    int idx = blockIdx.x * 256 + threadIdx.x;   // 0 .. 2*1024*1024-1
    int which = idx >> 20;
    int oh = idx & ((1 << 20) - 1);
    int o = oh >> 10, h = oh & 1023;
    const float* w = which ? wD : wA;
    __half* W = g_wc + (size_t)which * HH * 3072;
    const float* p = w + ((size_t)o * HH + h) * 3;
#pragma unroll
    for (int d = 0; d < 3; d++)
        W[(size_t)o * 3072 + d * 1024 + h] = __float2half_rn(p[d]);
}

__global__ void prep_out_w(const float* __restrict__ w) {
    int idx = blockIdx.x * 256 + threadIdx.x;  // 0..1M-1
    g_wo[idx] = __float2half_rn(w[idx]);
}

// zero padding rows (padrow 0 and 1025 of each batch)
__global__ void zero_pad_kernel() {
    int b = blockIdx.x >> 1;
    int top = blockIdx.x & 1;
    size_t off = ((size_t)b * MP + (top ? 1025 : 0)) * HH + threadIdx.x * 4;
    uint2 z = make_uint2(0u, 0u);
    *(uint2*)(g_ca + off) = z;
    *(uint2*)(g_cd + off) = z;
}

// ---------------- DWT -> fp16 (padded rows) ----------------
__global__ void dwt_kernel(const float* __restrict__ x) {
    int bm = blockIdx.x;
    int b = bm >> 10, m = bm & 1023;
    int h = threadIdx.x << 2;
    int s0 = 2 * m - 2, s1 = 2 * m - 1;
    if (s0 < 0) s0 = -s0 - 1;
    if (s1 < 0) s1 = -s1 - 1;
    const float* xb = x + (size_t)b * SS * HH + h;
    float4 v0 = *(const float4*)(xb + (size_t)s0 * HH);
    float4 v1 = *(const float4*)(xb + (size_t)s1 * HH);
    float4 v2 = *(const float4*)(xb + (size_t)(2 * m) * HH);
    float4 v3 = *(const float4*)(xb + (size_t)(2 * m + 1) * HH);
    __half ca[4], cd[4];
    ca[0] = __float2half_rn(C_H0 * v0.x + C_H1 * v1.x + C_H2 * v2.x + C_H3 * v3.x);
    ca[1] = __float2half_rn(C_H0 * v0.y + C_H1 * v1.y + C_H2 * v2.y + C_H3 * v3.y);
    ca[2] = __float2half_rn(C_H0 * v0.z + C_H1 * v1.z + C_H2 * v2.z + C_H3 * v3.z);
    ca[3] = __float2half_rn(C_H0 * v0.w + C_H1 * v1.w + C_H2 * v2.w + C_H3 * v3.w);
    cd[0] = __float2half_rn(C_H3 * v0.x - C_H2 * v1.x + C_H1 * v2.x - C_H0 * v3.x);
    cd[1] = __float2half_rn(C_H3 * v0.y - C_H2 * v1.y + C_H1 * v2.y - C_H0 * v3.y);
    cd[2] = __float2half_rn(C_H3 * v0.z - C_H2 * v1.z + C_H1 * v2.z - C_H0 * v3.z);
    cd[3] = __float2half_rn(C_H3 * v0.w - C_H2 * v1.w + C_H1 * v2.w - C_H0 * v3.w);
    size_t off = ((size_t)b * MP + m + 1) * HH + h;
    *(uint2*)(g_ca + off) = *(const uint2*)ca;
    *(uint2*)(g_cd + off) = *(const uint2*)cd;
}

// ---------------- iDWT: fp32 pa/pd -> fp16 recon ----------------
__global__ void idwt_kernel() {
    int bn = blockIdx.x;
    int b = bn >> 11, n = bn & 2047;
    int h = threadIdx.x << 2;
    size_t outoff = ((size_t)b * SS + n) * HH + h;
    if (n >= 2046) {
        *(uint2*)(g_rec + outoff) = make_uint2(0u, 0u);
        return;
    }
    int m0, m1;
    float wa0, wa1, wd0, wd1;
    if (!(n & 1)) {
        m0 = n >> 1; m1 = m0 + 1;
        wa1 = C_H0; wa0 = C_H2; wd1 = C_H3; wd0 = C_H1;
    } else {
        m0 = (n - 1) >> 1; m1 = m0 + 1;
        wa1 = C_H1; wa0 = C_H3; wd1 = -C_H2; wd0 = -C_H0;
    }
    size_t base = (size_t)b * MM * HH + h;
    float4 pa0 = *(const float4*)(g_pa + base + (size_t)m0 * HH);
    float4 pa1 = *(const float4*)(g_pa + base + (size_t)m1 * HH);
    float4 pd0 = *(const float4*)(g_pd + base + (size_t)m0 * HH);
    float4 pd1 = *(const float4*)(g_pd + base + (size_t)m1 * HH);
    __half rv[4];
    rv[0] = __float2half_rn(wa0 * pa0.x + wa1 * pa1.x + wd0 * pd0.x + wd1 * pd1.x);
    rv[1] = __float2half_rn(wa0 * pa0.y + wa1 * pa1.y + wd0 * pd0.y + wd1 * pd1.y);
    rv[2] = __float2half_rn(wa0 * pa0.z + wa1 * pa1.z + wd0 * pd0.z + wd1 * pd1.z);
    rv[3] = __float2half_rn(wa0 * pa0.w + wa1 * pa1.w + wd0 * pd0.w + wd1 * pd1.w);
    *(uint2*)(g_rec + outoff) = *(const uint2*)rv;
}

// ---------------------------------------------------------------------------
// fp16 GEMM via mma.sync m16n8k16: C[M,1024] = A[M,K] * B[1024,K]^T (+bias, opt GELU)
// conv: A row r -> padded activation row (r>>10)*1026 + (r&1023); K runs over
//       delta*1024+h, which is CONTIGUOUS in the padded layout.
// ---------------------------------------------------------------------------
__global__ __launch_bounds__(256, 1)
void gemm_f16(const __half* __restrict__ A, const __half* __restrict__ B,
              const float* __restrict__ bias, float* __restrict__ C,
              int kChunks, int ldb, int conv, int gelu) {
    extern __shared__ __align__(128) char smem[];
    const uint32_t sbase = smem_u32(smem);

    const int tid = threadIdx.x;
    const int lane = tid & 31;
    const int wid = tid >> 5;
    const int row0 = blockIdx.y << 7;
    const int col0 = blockIdx.x << 7;

    // ---- loader setup: each thread loads 32B of one A row + one B row per stage
    const int lrow = tid >> 1;            // 0..127
    const int lsel = tid & 1;             // which 16-half half of the row
    const int grow = row0 + lrow;
    const size_t aoff = conv ? ((size_t)(grow >> 10) * MP + (grow & 1023)) * HH
                             : (size_t)grow * HH;
    const __half* srcA = A + aoff + lsel * 16;
    const __half* srcB = B + (size_t)(col0 + lrow) * ldb + lsel * 16;
    const uint32_t dstA = sbase + lrow * ROWB + lsel * 32;
    const uint32_t dstB = dstA + TILEB;

    // ---- ldmatrix lane addresses
    const int wm = (wid >> 2) * 64;       // warp m offset
    const int wn = (wid & 3) * 32;        // warp n offset
    const uint32_t aLane = sbase + (uint32_t)(wm + (lane & 15)) * ROWB + ((lane >> 4) << 4);
    const uint32_t bLane = sbase + TILEB +
        (uint32_t)(wn + (lane & 7) + ((lane >> 4) << 3)) * ROWB + (((lane >> 3) & 1) << 4);

    float acc[4][4][4];
#pragma unroll
    for (int i = 0; i < 4; i++)
#pragma unroll
        for (int j = 0; j < 4; j++)
#pragma unroll
            for (int e = 0; e < 4; e++) acc[i][j][e] = 0.0f;

    // ---- prologue: stages 0,1
#pragma unroll
    for (int s = 0; s < 2; s++) {
        const __half* sa = srcA + s * BK;
        const __half* sb = srcB + s * BK;
        uint32_t da = dstA + s * STAGEB;
        uint32_t db = dstB + s * STAGEB;
        cp16(da, sa);       cp16(da + 16, sa + 8);
        cp16(db, sb);       cp16(db + 16, sb + 8);
        asm volatile("cp.async.commit_group;");
    }

    for (int c = 0; c < kChunks; c++) {
        if (c + 1 == kChunks) asm volatile("cp.async.wait_group 0;");
        else                  asm volatile("cp.async.wait_group 1;");
        __syncthreads();

        // issue loads for chunk c+2
        if (c + 2 < kChunks) {
            const int s = (c + 2) % STAGES;
            const __half* sa = srcA + (size_t)(c + 2) * BK;
            const __half* sb = srcB + (size_t)(c + 2) * BK;
            uint32_t da = dstA + s * STAGEB;
            uint32_t db = dstB + s * STAGEB;
            cp16(da, sa);       cp16(da + 16, sa + 8);
            cp16(db, sb);       cp16(db + 16, sb + 8);
            asm volatile("cp.async.commit_group;");
        }

        // compute on stage c%STAGES
        const uint32_t so = (c % STAGES) * STAGEB;
#pragma unroll
        for (int kk = 0; kk < 2; kk++) {
            uint32_t af[4][4];
#pragma unroll
            for (int mt = 0; mt < 4; mt++)
                ldm_x4(af[mt][0], af[mt][1], af[mt][2], af[mt][3],
                       aLane + so + mt * (16 * ROWB) + kk * 32);
            uint32_t bf[4][2];
#pragma unroll
            for (int nt2 = 0; nt2 < 2; nt2++)
                ldm_x4(bf[2 * nt2][0], bf[2 * nt2][1], bf[2 * nt2 + 1][0], bf[2 * nt2 + 1][1],
                       bLane + so + nt2 * (16 * ROWB) + kk * 32);
#pragma unroll
            for (int mt = 0; mt < 4; mt++)
#pragma unroll
                for (int nt = 0; nt < 4; nt++)
                    mma16816(acc[mt][nt], af[mt], bf[nt]);
        }
    }

    // ---- epilogue
    const int g = lane >> 2, t4 = lane & 3;
#pragma unroll
    for (int mt = 0; mt < 4; mt++) {
        const int m = row0 + wm + mt * 16 + g;
        float* crow0 = C + (size_t)m * HH;
        float* crow1 = crow0 + 8 * HH;
#pragma unroll
        for (int nt = 0; nt < 4; nt++) {
            const int n = col0 + wn + nt * 8 + 2 * t4;
            const float b0 = bias[n], b1 = bias[n + 1];
            float v0 = acc[mt][nt][0] + b0;
            float v1 = acc[mt][nt][1] + b1;
            float v2 = acc[mt][nt][2] + b0;
            float v3 = acc[mt][nt][3] + b1;
            if (gelu) {
                v0 = gelu_exact(v0); v1 = gelu_exact(v1);
                v2 = gelu_exact(v2); v3 = gelu_exact(v3);
            }
            *(float2*)(crow0 + n) = make_float2(v0, v1);
            *(float2*)(crow1 + n) = make_float2(v2, v3);
        }
    }
}

// ---------------------------------------------------------------------------
extern "C" void kernel_launch(void* const* d_in, const int* in_sizes, int n_in,
                              void* d_out, int out_size) {
    const float* x        = (const float*)d_in[0];
    const float* w_approx = (const float*)d_in[1];
    const float* b_approx = (const float*)d_in[2];
    const float* w_detail = (const float*)d_in[3];
    const float* b_detail = (const float*)d_in[4];
    const float* w_out    = (const float*)d_in[5];
    const float* b_out    = (const float*)d_in[6];
    float* out = (float*)d_out;

    cudaFuncSetAttribute(gemm_f16, cudaFuncAttributeMaxDynamicSharedMemorySize, SMEM_BYTES);

    void *p_ca, *p_cd, *p_pa, *p_pd, *p_rec, *p_wc, *p_wo;
    cudaGetSymbolAddress(&p_ca, g_ca);
    cudaGetSymbolAddress(&p_cd, g_cd);
    cudaGetSymbolAddress(&p_pa, g_pa);
    cudaGetSymbolAddress(&p_pd, g_pd);
    cudaGetSymbolAddress(&p_rec, g_rec);
    cudaGetSymbolAddress(&p_wc, g_wc);
    cudaGetSymbolAddress(&p_wo, g_wo);

    prep_conv_w<<<8192, 256>>>(w_approx, w_detail);
    prep_out_w<<<4096, 256>>>(w_out);
    zero_pad_kernel<<<16, 256>>>();
    dwt_kernel<<<NB * MM, 256>>>(x);

    // conv GEMMs: M=8192, N=1024, K=3072
    gemm_f16<<<dim3(8, 64), 256, SMEM_BYTES>>>(
        (const __half*)p_ca, (const __half*)p_wc, b_approx, (float*)p_pa,
        96, 3072, 1, 1);
    gemm_f16<<<dim3(8, 64), 256, SMEM_BYTES>>>(
        (const __half*)p_cd, (const __half*)p_wc + (size_t)HH * 3072, b_detail, (float*)p_pd,
        96, 3072, 1, 1);

    idwt_kernel<<<NB * SS, 256>>>();

    // out GEMM: M=16384, N=1024, K=1024
    gemm_f16<<<dim3(8, 128), 256, SMEM_BYTES>>>(
        (const __half*)p_rec, (const __half*)p_wo, b_out, out,
        32, 1024, 0, 0);
}

// round 4
// speedup vs baseline: 6.9786x; 1.4227x over previous
#include <cuda_runtime.h>
#include <cuda_fp16.h>
#include <math.h>
#include <stdint.h>

#define NB 8
#define SS 2048
#define HH 1024
#define MM 1024
#define MP 1026   // padded rows per batch (zero row below m=0 and above m=1023)

#define C_H0 0.48296291314469025f
#define C_H1 0.83651630373780790f
#define C_H2 0.22414386804185735f
#define C_H3 (-0.12940952255092145f)

// GEMM tiling
#define BK 32
#define STAGES 3
#define ROWB 80              // bytes per SMEM tile row (32 halves + 8 pad)
#define TILEB (128 * ROWB)   // 10240 bytes per operand tile
#define STAGEB (2 * TILEB)   // A + B per stage
#define SMEM_BYTES (STAGES * STAGEB)

// ---------------- device scratch ----------------
__device__ __align__(16) __half g_ca[NB * MP * HH];
__device__ __align__(16) __half g_cd[NB * MP * HH];
__device__ __align__(16) float  g_pa[NB * MM * HH];
__device__ __align__(16) float  g_pd[NB * MM * HH];
__device__ __align__(16) __half g_rec[NB * SS * HH];
__device__ __align__(16) __half g_wc[2 * HH * 3072];  // [which][o][delta*1024+h]
__device__ __align__(16) __half g_wo[HH * HH];        // [o][h]

// ---------------- helpers ----------------
__device__ __forceinline__ uint32_t smem_u32(const void* p) {
    uint32_t a;
    asm("{ .reg .u64 t; cvta.to.shared.u64 t, %1; cvt.u32.u64 %0, t; }" : "=r"(a) : "l"(p));
    return a;
}

__device__ __forceinline__ void cp16(uint32_t dst, const void* src) {
    asm volatile("cp.async.cg.shared.global [%0], [%1], 16;" :: "r"(dst), "l"(src));
}

__device__ __forceinline__ void ldm_x4(uint32_t& r0, uint32_t& r1, uint32_t& r2, uint32_t& r3,
                                       uint32_t addr) {
    asm volatile("ldmatrix.sync.aligned.m8n8.x4.shared.b16 {%0,%1,%2,%3}, [%4];"
                 : "=r"(r0), "=r"(r1), "=r"(r2), "=r"(r3) : "r"(addr));
}

__device__ __forceinline__ void mma16816(float* d, const uint32_t* a, const uint32_t* b) {
    asm volatile(
        "mma.sync.aligned.m16n8k16.row.col.f32.f16.f16.f32 "
        "{%0,%1,%2,%3}, {%4,%5,%6,%7}, {%8,%9}, {%0,%1,%2,%3};"
        : "+f"(d[0]), "+f"(d[1]), "+f"(d[2]), "+f"(d[3])
        : "r"(a[0]), "r"(a[1]), "r"(a[2]), "r"(a[3]), "r"(b[0]), "r"(b[1]));
}

__device__ __forceinline__ float gelu_exact(float v) {
    return 0.5f * v * (1.0f + erff(v * 0.70710678118654752f));
}

// ---------------- weight prep ----------------
__global__ void prep_conv_w(const float* __restrict__ wA, const float* __restrict__ wD) {
    int idx = blockIdx.x * 256 + threadIdx.x;   // 0 .. 2*1024*1024-1
    int which = idx >> 20;
    int oh = idx & ((1 << 20) - 1);
    int o = oh >> 10, h = oh & 1023;
    const float* w = which ? wD : wA;
    __half* W = g_wc + (size_t)which * HH * 3072;
    const float* p = w + ((size_t)o * HH + h) * 3;
#pragma unroll
    for (int d = 0; d < 3; d++)
        W[(size_t)o * 3072 + d * 1024 + h] = __float2half_rn(p[d]);
}

__global__ void prep_out_w(const float* __restrict__ w) {
    int idx = blockIdx.x * 256 + threadIdx.x;  // 0..1M-1
    g_wo[idx] = __float2half_rn(w[idx]);
}

// zero padding rows (padrow 0 and 1025 of each batch)
__global__ void zero_pad_kernel() {
    int b = blockIdx.x >> 1;
    int top = blockIdx.x & 1;
    size_t off = ((size_t)b * MP + (top ? 1025 : 0)) * HH + threadIdx.x * 4;
    uint2 z = make_uint2(0u, 0u);
    *(uint2*)(g_ca + off) = z;
    *(uint2*)(g_cd + off) = z;
}

// ---------------- DWT -> fp16 (padded rows) ----------------
__global__ void dwt_kernel(const float* __restrict__ x) {
    int bm = blockIdx.x;
    int b = bm >> 10, m = bm & 1023;
    int h = threadIdx.x << 2;
    int s0 = 2 * m - 2, s1 = 2 * m - 1;
    if (s0 < 0) s0 = -s0 - 1;
    if (s1 < 0) s1 = -s1 - 1;
    const float* xb = x + (size_t)b * SS * HH + h;
    float4 v0 = *(const float4*)(xb + (size_t)s0 * HH);
    float4 v1 = *(const float4*)(xb + (size_t)s1 * HH);
    float4 v2 = *(const float4*)(xb + (size_t)(2 * m) * HH);
    float4 v3 = *(const float4*)(xb + (size_t)(2 * m + 1) * HH);
    __half ca[4], cd[4];
    ca[0] = __float2half_rn(C_H0 * v0.x + C_H1 * v1.x + C_H2 * v2.x + C_H3 * v3.x);
    ca[1] = __float2half_rn(C_H0 * v0.y + C_H1 * v1.y + C_H2 * v2.y + C_H3 * v3.y);
    ca[2] = __float2half_rn(C_H0 * v0.z + C_H1 * v1.z + C_H2 * v2.z + C_H3 * v3.z);
    ca[3] = __float2half_rn(C_H0 * v0.w + C_H1 * v1.w + C_H2 * v2.w + C_H3 * v3.w);
    cd[0] = __float2half_rn(C_H3 * v0.x - C_H2 * v1.x + C_H1 * v2.x - C_H0 * v3.x);
    cd[1] = __float2half_rn(C_H3 * v0.y - C_H2 * v1.y + C_H1 * v2.y - C_H0 * v3.y);
    cd[2] = __float2half_rn(C_H3 * v0.z - C_H2 * v1.z + C_H1 * v2.z - C_H0 * v3.z);
    cd[3] = __float2half_rn(C_H3 * v0.w - C_H2 * v1.w + C_H1 * v2.w - C_H0 * v3.w);
    size_t off = ((size_t)b * MP + m + 1) * HH + h;
    *(uint2*)(g_ca + off) = *(const uint2*)ca;
    *(uint2*)(g_cd + off) = *(const uint2*)cd;
}

// ---------------- iDWT: fp32 pa/pd -> fp16 recon ----------------
__global__ void idwt_kernel() {
    int bn = blockIdx.x;
    int b = bn >> 11, n = bn & 2047;
    int h = threadIdx.x << 2;
    size_t outoff = ((size_t)b * SS + n) * HH + h;
    if (n >= 2046) {
        *(uint2*)(g_rec + outoff) = make_uint2(0u, 0u);
        return;
    }
    int m0, m1;
    float wa0, wa1, wd0, wd1;
    if (!(n & 1)) {
        m0 = n >> 1; m1 = m0 + 1;
        wa1 = C_H0; wa0 = C_H2; wd1 = C_H3; wd0 = C_H1;
    } else {
        m0 = (n - 1) >> 1; m1 = m0 + 1;
        wa1 = C_H1; wa0 = C_H3; wd1 = -C_H2; wd0 = -C_H0;
    }
    size_t base = (size_t)b * MM * HH + h;
    float4 pa0 = *(const float4*)(g_pa + base + (size_t)m0 * HH);
    float4 pa1 = *(const float4*)(g_pa + base + (size_t)m1 * HH);
    float4 pd0 = *(const float4*)(g_pd + base + (size_t)m0 * HH);
    float4 pd1 = *(const float4*)(g_pd + base + (size_t)m1 * HH);
    __half rv[4];
    rv[0] = __float2half_rn(wa0 * pa0.x + wa1 * pa1.x + wd0 * pd0.x + wd1 * pd1.x);
    rv[1] = __float2half_rn(wa0 * pa0.y + wa1 * pa1.y + wd0 * pd0.y + wd1 * pd1.y);
    rv[2] = __float2half_rn(wa0 * pa0.z + wa1 * pa1.z + wd0 * pd0.z + wd1 * pd1.z);
    rv[3] = __float2half_rn(wa0 * pa0.w + wa1 * pa1.w + wd0 * pd0.w + wd1 * pd1.w);
    *(uint2*)(g_rec + outoff) = *(const uint2*)rv;
}

// ---------------------------------------------------------------------------
// Shared fp16 GEMM body via mma.sync m16n8k16:
// C[M,1024] = A[M,K] * B[1024,K]^T (+bias, opt GELU)
// ---------------------------------------------------------------------------
template <bool CONV, bool GELU>
__device__ __forceinline__ void gemm_body(
    const __half* __restrict__ A, const __half* __restrict__ B,
    const float* __restrict__ bias, float* __restrict__ C,
    int kChunks, int ldb, char* smem) {

    const uint32_t sbase = smem_u32(smem);

    const int tid = threadIdx.x;
    const int lane = tid & 31;
    const int wid = tid >> 5;
    const int row0 = blockIdx.y << 7;
    const int col0 = blockIdx.x << 7;

    // ---- loader setup: each thread loads 32B of one A row + one B row per stage
    const int lrow = tid >> 1;            // 0..127
    const int lsel = tid & 1;             // which 16-half half of the row
    const int grow = row0 + lrow;
    const size_t aoff = CONV ? ((size_t)(grow >> 10) * MP + (grow & 1023)) * HH
                             : (size_t)grow * HH;
    const __half* srcA = A + aoff + lsel * 16;
    const __half* srcB = B + (size_t)(col0 + lrow) * ldb + lsel * 16;
    const uint32_t dstA = sbase + lrow * ROWB + lsel * 32;
    const uint32_t dstB = dstA + TILEB;

    // ---- ldmatrix lane addresses
    const int wm = (wid >> 2) * 64;       // warp m offset
    const int wn = (wid & 3) * 32;        // warp n offset
    const uint32_t aLane = sbase + (uint32_t)(wm + (lane & 15)) * ROWB + ((lane >> 4) << 4);
    const uint32_t bLane = sbase + TILEB +
        (uint32_t)(wn + (lane & 7) + ((lane >> 4) << 3)) * ROWB + (((lane >> 3) & 1) << 4);

    float acc[4][4][4];
#pragma unroll
    for (int i = 0; i < 4; i++)
#pragma unroll
        for (int j = 0; j < 4; j++)
#pragma unroll
            for (int e = 0; e < 4; e++) acc[i][j][e] = 0.0f;

    // ---- prologue: stages 0,1
#pragma unroll
    for (int s = 0; s < 2; s++) {
        const __half* sa = srcA + s * BK;
        const __half* sb = srcB + s * BK;
        uint32_t da = dstA + s * STAGEB;
        uint32_t db = dstB + s * STAGEB;
        cp16(da, sa);       cp16(da + 16, sa + 8);
        cp16(db, sb);       cp16(db + 16, sb + 8);
        asm volatile("cp.async.commit_group;");
    }

    for (int c = 0; c < kChunks; c++) {
        if (c + 1 == kChunks) asm volatile("cp.async.wait_group 0;");
        else                  asm volatile("cp.async.wait_group 1;");
        __syncthreads();

        // issue loads for chunk c+2
        if (c + 2 < kChunks) {
            const int s = (c + 2) % STAGES;
            const __half* sa = srcA + (size_t)(c + 2) * BK;
            const __half* sb = srcB + (size_t)(c + 2) * BK;
            uint32_t da = dstA + s * STAGEB;
            uint32_t db = dstB + s * STAGEB;
            cp16(da, sa);       cp16(da + 16, sa + 8);
            cp16(db, sb);       cp16(db + 16, sb + 8);
            asm volatile("cp.async.commit_group;");
        }

        // compute on stage c%STAGES
        const uint32_t so = (c % STAGES) * STAGEB;
#pragma unroll
        for (int kk = 0; kk < 2; kk++) {
            uint32_t af[4][4];
#pragma unroll
            for (int mt = 0; mt < 4; mt++)
                ldm_x4(af[mt][0], af[mt][1], af[mt][2], af[mt][3],
                       aLane + so + mt * (16 * ROWB) + kk * 32);
            uint32_t bf[4][2];
#pragma unroll
            for (int nt2 = 0; nt2 < 2; nt2++)
                ldm_x4(bf[2 * nt2][0], bf[2 * nt2][1], bf[2 * nt2 + 1][0], bf[2 * nt2 + 1][1],
                       bLane + so + nt2 * (16 * ROWB) + kk * 32);
#pragma unroll
            for (int mt = 0; mt < 4; mt++)
#pragma unroll
                for (int nt = 0; nt < 4; nt++)
                    mma16816(acc[mt][nt], af[mt], bf[nt]);
        }
    }

    // ---- epilogue
    const int g = lane >> 2, t4 = lane & 3;
#pragma unroll
    for (int mt = 0; mt < 4; mt++) {
        const int m = row0 + wm + mt * 16 + g;
        float* crow0 = C + (size_t)m * HH;
        float* crow1 = crow0 + 8 * HH;
#pragma unroll
        for (int nt = 0; nt < 4; nt++) {
            const int n = col0 + wn + nt * 8 + 2 * t4;
            const float b0 = bias[n], b1 = bias[n + 1];
            float v0 = acc[mt][nt][0] + b0;
            float v1 = acc[mt][nt][1] + b1;
            float v2 = acc[mt][nt][2] + b0;
            float v3 = acc[mt][nt][3] + b1;
            if (GELU) {
                v0 = gelu_exact(v0); v1 = gelu_exact(v1);
                v2 = gelu_exact(v2); v3 = gelu_exact(v3);
            }
            *(float2*)(crow0 + n) = make_float2(v0, v1);
            *(float2*)(crow1 + n) = make_float2(v2, v3);
        }
    }
}

// conv GEMMs merged: grid.z selects approx (0) / detail (1)
__global__ __launch_bounds__(256, 2)
void conv_gemm(const float* __restrict__ bias_a, const float* __restrict__ bias_d) {
    extern __shared__ __align__(128) char smem[];
    const int which = blockIdx.z;
    const __half* A = which ? g_cd : g_ca;
    const __half* B = g_wc + (size_t)which * HH * 3072;
    const float* bias = which ? bias_d : bias_a;
    float* C = which ? g_pd : g_pa;
    gemm_body<true, true>(A, B, bias, C, 96, 3072, smem);
}

__global__ __launch_bounds__(256, 2)
void out_gemm(const float* __restrict__ b_out, float* __restrict__ out) {
    extern __shared__ __align__(128) char smem[];
    gemm_body<false, false>(g_rec, g_wo, b_out, out, 32, 1024, smem);
}

// ---------------------------------------------------------------------------
extern "C" void kernel_launch(void* const* d_in, const int* in_sizes, int n_in,
                              void* d_out, int out_size) {
    const float* x        = (const float*)d_in[0];
    const float* w_approx = (const float*)d_in[1];
    const float* b_approx = (const float*)d_in[2];
    const float* w_detail = (const float*)d_in[3];
    const float* b_detail = (const float*)d_in[4];
    const float* w_out    = (const float*)d_in[5];
    const float* b_out    = (const float*)d_in[6];
    float* out = (float*)d_out;

    cudaFuncSetAttribute(conv_gemm, cudaFuncAttributeMaxDynamicSharedMemorySize, SMEM_BYTES);
    cudaFuncSetAttribute(out_gemm, cudaFuncAttributeMaxDynamicSharedMemorySize, SMEM_BYTES);

    prep_conv_w<<<8192, 256>>>(w_approx, w_detail);
    prep_out_w<<<4096, 256>>>(w_out);
    zero_pad_kernel<<<16, 256>>>();
    dwt_kernel<<<NB * MM, 256>>>(x);

    // conv GEMMs: M=8192, N=1024, K=3072, both halves in one launch
    conv_gemm<<<dim3(8, 64, 2), 256, SMEM_BYTES>>>(b_approx, b_detail);

    idwt_kernel<<<NB * SS, 256>>>();

    // out GEMM: M=16384, N=1024, K=1024
    out_gemm<<<dim3(8, 128), 256, SMEM_BYTES>>>(b_out, out);
}

// round 5
// speedup vs baseline: 10.0342x; 1.4379x over previous
#include <cuda_runtime.h>
#include <cuda.h>
#include <cuda_fp16.h>
#include <math.h>
#include <stdint.h>

#define NB 8
#define SS 2048
#define HH 1024
#define MM 1024
#define MP 1026   // padded rows per batch (zero row below m=0 and above m=1023)

#define C_H0 0.48296291314469025f
#define C_H1 0.83651630373780790f
#define C_H2 0.22414386804185735f
#define C_H3 (-0.12940952255092145f)

// GEMM tiling: CTA 128x128, BK=32, 3-stage TMA pipeline
#define BK 32
#define TILEB 8192            // 128 rows x 64B per operand tile
#define STAGEB (2 * TILEB)    // A + B
#define SMEM_BYTES (3 * STAGEB + 64)

// ---------------- device scratch ----------------
__device__ __align__(16) __half g_ca[NB * MP * HH];
__device__ __align__(16) __half g_cd[NB * MP * HH];
__device__ __align__(16) float  g_pa[NB * MM * HH];
__device__ __align__(16) float  g_pd[NB * MM * HH];
__device__ __align__(16) __half g_rec[NB * SS * HH];
__device__ __align__(16) __half g_wc[2 * HH * 3072];  // [which][o][delta*1024+h]
__device__ __align__(16) __half g_wo[HH * HH];        // [o][h]

// ---------------- helpers ----------------
__device__ __forceinline__ uint32_t smem_u32(const void* p) {
    uint32_t a;
    asm("{ .reg .u64 t; cvta.to.shared.u64 t, %1; cvt.u32.u64 %0, t; }" : "=r"(a) : "l"(p));
    return a;
}

__device__ __forceinline__ uint32_t sw64(uint32_t o) {   // SW64: bits[5:4] ^= bits[8:7]
    return o ^ ((o >> 3) & 0x30);
}

__device__ __forceinline__ void ldm_x4(uint32_t& r0, uint32_t& r1, uint32_t& r2, uint32_t& r3,
                                       uint32_t addr) {
    asm volatile("ldmatrix.sync.aligned.m8n8.x4.shared.b16 {%0,%1,%2,%3}, [%4];"
                 : "=r"(r0), "=r"(r1), "=r"(r2), "=r"(r3) : "r"(addr));
}

__device__ __forceinline__ void mma16816(float* d, const uint32_t* a, const uint32_t* b) {
    asm volatile(
        "mma.sync.aligned.m16n8k16.row.col.f32.f16.f16.f32 "
        "{%0,%1,%2,%3}, {%4,%5,%6,%7}, {%8,%9}, {%0,%1,%2,%3};"
        : "+f"(d[0]), "+f"(d[1]), "+f"(d[2]), "+f"(d[3])
        : "r"(a[0]), "r"(a[1]), "r"(a[2]), "r"(a[3]), "r"(b[0]), "r"(b[1]));
}

__device__ __forceinline__ void tma2d(uint32_t dst, const CUtensorMap* tm, int x, int y,
                                      uint32_t mb) {
    asm volatile(
        "cp.async.bulk.tensor.2d.shared::cta.global.tile.mbarrier::complete_tx::bytes "
        "[%0], [%1, {%2, %3}], [%4];"
        :: "r"(dst), "l"(tm), "r"(x), "r"(y), "r"(mb) : "memory");
}

__device__ __forceinline__ void mbar_init(uint32_t mb, uint32_t cnt) {
    asm volatile("mbarrier.init.shared.b64 [%0], %1;" :: "r"(mb), "r"(cnt) : "memory");
}

__device__ __forceinline__ void mbar_expect(uint32_t mb, uint32_t bytes) {
    asm volatile("mbarrier.arrive.expect_tx.shared.b64 _, [%0], %1;"
                 :: "r"(mb), "r"(bytes) : "memory");
}

__device__ __forceinline__ void mbar_wait(uint32_t mb, uint32_t parity) {
    asm volatile(
        "{\n\t.reg .pred P;\n\t"
        "LAB_%=:\n\t"
        "mbarrier.try_wait.parity.acquire.cta.shared::cta.b64 P, [%0], %1, 0x989680;\n\t"
        "@!P bra LAB_%=;\n\t"
        "}" :: "r"(mb), "r"(parity) : "memory");
}

__device__ __forceinline__ float gelu_exact(float v) {
    return 0.5f * v * (1.0f + erff(v * 0.70710678118654752f));
}

// ---------------- weight prep ----------------
__global__ void prep_conv_w(const float* __restrict__ wA, const float* __restrict__ wD) {
    int idx = blockIdx.x * 256 + threadIdx.x;   // 0 .. 2*1024*1024-1
    int which = idx >> 20;
    int oh = idx & ((1 << 20) - 1);
    int o = oh >> 10, h = oh & 1023;
    const float* w = which ? wD : wA;
    __half* W = g_wc + (size_t)which * HH * 3072;
    const float* p = w + ((size_t)o * HH + h) * 3;
#pragma unroll
    for (int d = 0; d < 3; d++)
        W[(size_t)o * 3072 + d * 1024 + h] = __float2half_rn(p[d]);
}

__global__ void prep_out_w(const float* __restrict__ w) {
    int idx = blockIdx.x * 256 + threadIdx.x;  // 0..1M-1
    g_wo[idx] = __float2half_rn(w[idx]);
}

// zero padding rows (padrow 0 and 1025 of each batch)
__global__ void zero_pad_kernel() {
    int b = blockIdx.x >> 1;
    int top = blockIdx.x & 1;
    size_t off = ((size_t)b * MP + (top ? 1025 : 0)) * HH + threadIdx.x * 4;
    uint2 z = make_uint2(0u, 0u);
    *(uint2*)(g_ca + off) = z;
    *(uint2*)(g_cd + off) = z;
}

// ---------------- DWT -> fp16 (padded rows) ----------------
__global__ void dwt_kernel(const float* __restrict__ x) {
    int bm = blockIdx.x;
    int b = bm >> 10, m = bm & 1023;
    int h = threadIdx.x << 2;
    int s0 = 2 * m - 2, s1 = 2 * m - 1;
    if (s0 < 0) s0 = -s0 - 1;
    if (s1 < 0) s1 = -s1 - 1;
    const float* xb = x + (size_t)b * SS * HH + h;
    float4 v0 = *(const float4*)(xb + (size_t)s0 * HH);
    float4 v1 = *(const float4*)(xb + (size_t)s1 * HH);
    float4 v2 = *(const float4*)(xb + (size_t)(2 * m) * HH);
    float4 v3 = *(const float4*)(xb + (size_t)(2 * m + 1) * HH);
    __half ca[4], cd[4];
    ca[0] = __float2half_rn(C_H0 * v0.x + C_H1 * v1.x + C_H2 * v2.x + C_H3 * v3.x);
    ca[1] = __float2half_rn(C_H0 * v0.y + C_H1 * v1.y + C_H2 * v2.y + C_H3 * v3.y);
    ca[2] = __float2half_rn(C_H0 * v0.z + C_H1 * v1.z + C_H2 * v2.z + C_H3 * v3.z);
    ca[3] = __float2half_rn(C_H0 * v0.w + C_H1 * v1.w + C_H2 * v2.w + C_H3 * v3.w);
    cd[0] = __float2half_rn(C_H3 * v0.x - C_H2 * v1.x + C_H1 * v2.x - C_H0 * v3.x);
    cd[1] = __float2half_rn(C_H3 * v0.y - C_H2 * v1.y + C_H1 * v2.y - C_H0 * v3.y);
    cd[2] = __float2half_rn(C_H3 * v0.z - C_H2 * v1.z + C_H1 * v2.z - C_H0 * v3.z);
    cd[3] = __float2half_rn(C_H3 * v0.w - C_H2 * v1.w + C_H1 * v2.w - C_H0 * v3.w);
    size_t off = ((size_t)b * MP + m + 1) * HH + h;
    *(uint2*)(g_ca + off) = *(const uint2*)ca;
    *(uint2*)(g_cd + off) = *(const uint2*)cd;
}

// ---------------- iDWT: fp32 pa/pd -> fp16 recon ----------------
__global__ void idwt_kernel() {
    int bn = blockIdx.x;
    int b = bn >> 11, n = bn & 2047;
    int h = threadIdx.x << 2;
    size_t outoff = ((size_t)b * SS + n) * HH + h;
    if (n >= 2046) {
        *(uint2*)(g_rec + outoff) = make_uint2(0u, 0u);
        return;
    }
    int m0, m1;
    float wa0, wa1, wd0, wd1;
    if (!(n & 1)) {
        m0 = n >> 1; m1 = m0 + 1;
        wa1 = C_H0; wa0 = C_H2; wd1 = C_H3; wd0 = C_H1;
    } else {
        m0 = (n - 1) >> 1; m1 = m0 + 1;
        wa1 = C_H1; wa0 = C_H3; wd1 = -C_H2; wd0 = -C_H0;
    }
    size_t base = (size_t)b * MM * HH + h;
    float4 pa0 = *(const float4*)(g_pa + base + (size_t)m0 * HH);
    float4 pa1 = *(const float4*)(g_pa + base + (size_t)m1 * HH);
    float4 pd0 = *(const float4*)(g_pd + base + (size_t)m0 * HH);
    float4 pd1 = *(const float4*)(g_pd + base + (size_t)m1 * HH);
    __half rv[4];
    rv[0] = __float2half_rn(wa0 * pa0.x + wa1 * pa1.x + wd0 * pd0.x + wd1 * pd1.x);
    rv[1] = __float2half_rn(wa0 * pa0.y + wa1 * pa1.y + wd0 * pd0.y + wd1 * pd1.y);
    rv[2] = __float2half_rn(wa0 * pa0.z + wa1 * pa1.z + wd0 * pd0.z + wd1 * pd1.z);
    rv[3] = __float2half_rn(wa0 * pa0.w + wa1 * pa1.w + wd0 * pd0.w + wd1 * pd1.w);
    *(uint2*)(g_rec + outoff) = *(const uint2*)rv;
}

// ---------------------------------------------------------------------------
// fp16 GEMM body, TMA-fed: C[M,1024] = A[M,K] * B[1024,K]^T (+bias, opt GELU)
// Stages: 3 x (A 8KB + B 8KB), SW64 swizzled by TMA.
// ---------------------------------------------------------------------------
template <bool CONV, bool GELU>
__device__ __forceinline__ void gemm_body(
    const CUtensorMap* __restrict__ tmA, const CUtensorMap* __restrict__ tmB,
    const float* __restrict__ bias, float* __restrict__ C,
    int kChunks, char* smem) {

    const uint32_t sbase = smem_u32(smem);
    const uint32_t mbars = sbase + 3 * STAGEB;

    const int tid = threadIdx.x;
    const int lane = tid & 31;
    const int wid = tid >> 5;
    const int row0 = blockIdx.y << 7;
    const int col0 = blockIdx.x << 7;
    const int arowBase = CONV ? ((row0 >> 10) * MP + (row0 & 1023)) : row0;

    if (tid == 0) {
        mbar_init(mbars + 0, 1);
        mbar_init(mbars + 8, 1);
        mbar_init(mbars + 16, 1);
    }
    __syncthreads();

    // prologue: stages 0,1
    if (tid == 0) {
#pragma unroll
        for (int c = 0; c < 2; c++) {
            const int k0 = c * BK;
            const uint32_t mb = mbars + c * 8;
            mbar_expect(mb, 2 * TILEB);
            const int ax = CONV ? (k0 & 1023) : k0;
            const int ay = CONV ? (arowBase + (k0 >> 10)) : arowBase;
            tma2d(sbase + c * STAGEB, tmA, ax, ay, mb);
            tma2d(sbase + c * STAGEB + TILEB, tmB, k0, col0, mb);
        }
    }

    // ldmatrix lane bases (logical offsets; swizzle applied per use)
    const int wm = (wid >> 2) * 64;       // warp m offset
    const int wn = (wid & 3) * 32;        // warp n offset
    const uint32_t aBase = (uint32_t)((wm + (lane & 15)) * 64 + ((lane >> 4) << 4));
    const uint32_t bBase = (uint32_t)((wn + (lane & 7) + ((lane >> 4) << 3)) * 64 +
                                      (((lane >> 3) & 1) << 4));

    float acc[4][4][4];
#pragma unroll
    for (int i = 0; i < 4; i++)
#pragma unroll
        for (int j = 0; j < 4; j++)
#pragma unroll
            for (int e = 0; e < 4; e++) acc[i][j][e] = 0.0f;

    for (int c = 0; c < kChunks; c++) {
        __syncthreads();   // all warps done with chunk c-1 -> stage (c+2)%3 reusable

        if (tid == 0 && c + 2 < kChunks) {
            const int c2 = c + 2;
            const int s2 = c2 % 3;
            const int k0 = c2 * BK;
            const uint32_t mb = mbars + s2 * 8;
            mbar_expect(mb, 2 * TILEB);
            const int ax = CONV ? (k0 & 1023) : k0;
            const int ay = CONV ? (arowBase + (k0 >> 10)) : arowBase;
            tma2d(sbase + s2 * STAGEB, tmA, ax, ay, mb);
            tma2d(sbase + s2 * STAGEB + TILEB, tmB, k0, col0, mb);
        }

        const int s = c % 3;
        mbar_wait(mbars + s * 8, (uint32_t)((c / 3) & 1));

        const uint32_t stA = sbase + s * STAGEB;
        const uint32_t stB = stA + TILEB;
#pragma unroll
        for (int kk = 0; kk < 2; kk++) {
            uint32_t af[4][4];
#pragma unroll
            for (int mt = 0; mt < 4; mt++) {
                const uint32_t lo = aBase + mt * (16 * 64) + kk * 32;
                ldm_x4(af[mt][0], af[mt][1], af[mt][2], af[mt][3], stA + sw64(lo));
            }
            uint32_t bf[4][2];
#pragma unroll
            for (int nt2 = 0; nt2 < 2; nt2++) {
                const uint32_t lo = bBase + nt2 * (16 * 64) + kk * 32;
                ldm_x4(bf[2 * nt2][0], bf[2 * nt2][1], bf[2 * nt2 + 1][0], bf[2 * nt2 + 1][1],
                       stB + sw64(lo));
            }
#pragma unroll
            for (int mt = 0; mt < 4; mt++)
#pragma unroll
                for (int nt = 0; nt < 4; nt++)
                    mma16816(acc[mt][nt], af[mt], bf[nt]);
        }
    }

    // ---- epilogue
    const int g = lane >> 2, t4 = lane & 3;
#pragma unroll
    for (int mt = 0; mt < 4; mt++) {
        const int m = row0 + wm + mt * 16 + g;
        float* crow0 = C + (size_t)m * HH;
        float* crow1 = crow0 + 8 * HH;
#pragma unroll
        for (int nt = 0; nt < 4; nt++) {
            const int n = col0 + wn + nt * 8 + 2 * t4;
            const float b0 = bias[n], b1 = bias[n + 1];
            float v0 = acc[mt][nt][0] + b0;
            float v1 = acc[mt][nt][1] + b1;
            float v2 = acc[mt][nt][2] + b0;
            float v3 = acc[mt][nt][3] + b1;
            if (GELU) {
                v0 = gelu_exact(v0); v1 = gelu_exact(v1);
                v2 = gelu_exact(v2); v3 = gelu_exact(v3);
            }
            *(float2*)(crow0 + n) = make_float2(v0, v1);
            *(float2*)(crow1 + n) = make_float2(v2, v3);
        }
    }
}

// conv GEMMs merged: grid.z selects approx (0) / detail (1)
__global__ __launch_bounds__(256, 2)
void conv_gemm(const __grid_constant__ CUtensorMap tmAca,
               const __grid_constant__ CUtensorMap tmAcd,
               const __grid_constant__ CUtensorMap tmBa,
               const __grid_constant__ CUtensorMap tmBd,
               const float* __restrict__ bias_a, const float* __restrict__ bias_d) {
    extern __shared__ __align__(1024) char smem[];
    const int which = blockIdx.z;
    const CUtensorMap* tA = which ? &tmAcd : &tmAca;
    const CUtensorMap* tB = which ? &tmBd : &tmBa;
    const float* bias = which ? bias_d : bias_a;
    float* C = which ? g_pd : g_pa;
    gemm_body<true, true>(tA, tB, bias, C, 96, smem);
}

__global__ __launch_bounds__(256, 2)
void out_gemm(const __grid_constant__ CUtensorMap tmA,
              const __grid_constant__ CUtensorMap tmB,
              const float* __restrict__ b_out, float* __restrict__ out) {
    extern __shared__ __align__(1024) char smem[];
    gemm_body<false, false>(&tmA, &tmB, b_out, out, 32, smem);
}

// ---------------------------------------------------------------------------
typedef CUresult (*PFN_encode)(
    CUtensorMap*, CUtensorMapDataType, cuuint32_t, void*,
    const cuuint64_t*, const cuuint64_t*, const cuuint32_t*, const cuuint32_t*,
    CUtensorMapInterleave, CUtensorMapSwizzle, CUtensorMapL2promotion,
    CUtensorMapFloatOOBfill);

static void enc2d(PFN_encode enc, CUtensorMap* tm, void* base,
                  unsigned long long inner, unsigned long long rows) {
    cuuint64_t dims[2] = {inner, rows};
    cuuint64_t strides[1] = {inner * 2};
    cuuint32_t box[2] = {32, 128};
    cuuint32_t es[2] = {1, 1};
    enc(tm, CU_TENSOR_MAP_DATA_TYPE_UINT16, 2, base, dims, strides, box, es,
        CU_TENSOR_MAP_INTERLEAVE_NONE, CU_TENSOR_MAP_SWIZZLE_64B,
        CU_TENSOR_MAP_L2_PROMOTION_L2_128B, CU_TENSOR_MAP_FLOAT_OOB_FILL_NONE);
}

extern "C" void kernel_launch(void* const* d_in, const int* in_sizes, int n_in,
                              void* d_out, int out_size) {
    const float* x        = (const float*)d_in[0];
    const float* w_approx = (const float*)d_in[1];
    const float* b_approx = (const float*)d_in[2];
    const float* w_detail = (const float*)d_in[3];
    const float* b_detail = (const float*)d_in[4];
    const float* w_out    = (const float*)d_in[5];
    const float* b_out    = (const float*)d_in[6];
    float* out = (float*)d_out;

    cudaFuncSetAttribute(conv_gemm, cudaFuncAttributeMaxDynamicSharedMemorySize, SMEM_BYTES);
    cudaFuncSetAttribute(out_gemm, cudaFuncAttributeMaxDynamicSharedMemorySize, SMEM_BYTES);

    void *p_ca, *p_cd, *p_rec, *p_wc, *p_wo;
    cudaGetSymbolAddress(&p_ca, g_ca);
    cudaGetSymbolAddress(&p_cd, g_cd);
    cudaGetSymbolAddress(&p_rec, g_rec);
    cudaGetSymbolAddress(&p_wc, g_wc);
    cudaGetSymbolAddress(&p_wo, g_wo);

    void* fn = nullptr;
    cudaDriverEntryPointQueryResult qr;
    cudaGetDriverEntryPoint("cuTensorMapEncodeTiled", &fn, cudaEnableDefault, &qr);
    PFN_encode enc = (PFN_encode)fn;

    CUtensorMap tmAca, tmAcd, tmBa, tmBd, tmArec, tmBo;
    enc2d(enc, &tmAca, p_ca, 1024, (unsigned long long)NB * MP);
    enc2d(enc, &tmAcd, p_cd, 1024, (unsigned long long)NB * MP);
    enc2d(enc, &tmBa, p_wc, 3072, 1024);
    enc2d(enc, &tmBd, (char*)p_wc + (size_t)HH * 3072 * 2, 3072, 1024);
    enc2d(enc, &tmArec, p_rec, 1024, (unsigned long long)NB * SS);
    enc2d(enc, &tmBo, p_wo, 1024, 1024);

    prep_conv_w<<<8192, 256>>>(w_approx, w_detail);
    prep_out_w<<<4096, 256>>>(w_out);
    zero_pad_kernel<<<16, 256>>>();
    dwt_kernel<<<NB * MM, 256>>>(x);

    // conv GEMMs: M=8192, N=1024, K=3072, both halves in one launch
    conv_gemm<<<dim3(8, 64, 2), 256, SMEM_BYTES>>>(tmAca, tmAcd, tmBa, tmBd,
                                                   b_approx, b_detail);

    idwt_kernel<<<NB * SS, 256>>>();

    // out GEMM: M=16384, N=1024, K=1024
    out_gemm<<<dim3(8, 128), 256, SMEM_BYTES>>>(tmArec, tmBo, b_out, out);
}

// round 6
// speedup vs baseline: 10.6698x; 1.0633x over previous
#include <cuda_runtime.h>
#include <cuda.h>
#include <cuda_fp16.h>
#include <math.h>
#include <stdint.h>

#define NB 8
#define SS 2048
#define HH 1024
#define MM 1024
#define MP 1026   // padded rows per batch (zero row below m=0 and above m=1023)

#define C_H0 0.48296291314469025f
#define C_H1 0.83651630373780790f
#define C_H2 0.22414386804185735f
#define C_H3 (-0.12940952255092145f)

// GEMM tiling: CTA 128x128, BK=64, 3-stage TMA pipeline, SW128
#define BK 64
#define TILEB 16384           // 128 rows x 128B per operand tile
#define STAGEB (2 * TILEB)    // A + B
#define SMEM_BYTES (3 * STAGEB + 64)

// ---------------- device scratch ----------------
__device__ __align__(16) __half g_ca[NB * MP * HH];
__device__ __align__(16) __half g_cd[NB * MP * HH];
__device__ __align__(16) float  g_pa[NB * MM * HH];
__device__ __align__(16) float  g_pd[NB * MM * HH];
__device__ __align__(16) __half g_rec[NB * SS * HH];
__device__ __align__(16) __half g_wc[2 * HH * 3072];  // [which][o][delta*1024+h]
__device__ __align__(16) __half g_wo[HH * HH];        // [o][h]

// ---------------- helpers ----------------
__device__ __forceinline__ uint32_t smem_u32(const void* p) {
    uint32_t a;
    asm("{ .reg .u64 t; cvta.to.shared.u64 t, %1; cvt.u32.u64 %0, t; }" : "=r"(a) : "l"(p));
    return a;
}

__device__ __forceinline__ uint32_t sw128(uint32_t o) {  // SW128: bits[6:4] ^= bits[9:7]
    return o ^ ((o >> 3) & 0x70);
}

__device__ __forceinline__ void ldm_x4(uint32_t& r0, uint32_t& r1, uint32_t& r2, uint32_t& r3,
                                       uint32_t addr) {
    asm volatile("ldmatrix.sync.aligned.m8n8.x4.shared.b16 {%0,%1,%2,%3}, [%4];"
                 : "=r"(r0), "=r"(r1), "=r"(r2), "=r"(r3) : "r"(addr));
}

__device__ __forceinline__ void mma16816(float* d, const uint32_t* a, const uint32_t* b) {
    asm volatile(
        "mma.sync.aligned.m16n8k16.row.col.f32.f16.f16.f32 "
        "{%0,%1,%2,%3}, {%4,%5,%6,%7}, {%8,%9}, {%0,%1,%2,%3};"
        : "+f"(d[0]), "+f"(d[1]), "+f"(d[2]), "+f"(d[3])
        : "r"(a[0]), "r"(a[1]), "r"(a[2]), "r"(a[3]), "r"(b[0]), "r"(b[1]));
}

__device__ __forceinline__ void tma2d(uint32_t dst, const CUtensorMap* tm, int x, int y,
                                      uint32_t mb) {
    asm volatile(
        "cp.async.bulk.tensor.2d.shared::cta.global.tile.mbarrier::complete_tx::bytes "
        "[%0], [%1, {%2, %3}], [%4];"
        :: "r"(dst), "l"(tm), "r"(x), "r"(y), "r"(mb) : "memory");
}

__device__ __forceinline__ void mbar_init(uint32_t mb, uint32_t cnt) {
    asm volatile("mbarrier.init.shared.b64 [%0], %1;" :: "r"(mb), "r"(cnt) : "memory");
}

__device__ __forceinline__ void mbar_expect(uint32_t mb, uint32_t bytes) {
    asm volatile("mbarrier.arrive.expect_tx.shared.b64 _, [%0], %1;"
                 :: "r"(mb), "r"(bytes) : "memory");
}

__device__ __forceinline__ void mbar_wait(uint32_t mb, uint32_t parity) {
    asm volatile(
        "{\n\t.reg .pred P;\n\t"
        "LAB_%=:\n\t"
        "mbarrier.try_wait.parity.acquire.cta.shared::cta.b64 P, [%0], %1, 0x989680;\n\t"
        "@!P bra LAB_%=;\n\t"
        "}" :: "r"(mb), "r"(parity) : "memory");
}

__device__ __forceinline__ float gelu_exact(float v) {
    return 0.5f * v * (1.0f + erff(v * 0.70710678118654752f));
}

// ---------------- weight prep ----------------
__global__ void prep_conv_w(const float* __restrict__ wA, const float* __restrict__ wD) {
    int idx = blockIdx.x * 256 + threadIdx.x;   // 0 .. 2*1024*1024-1
    int which = idx >> 20;
    int oh = idx & ((1 << 20) - 1);
    int o = oh >> 10, h = oh & 1023;
    const float* w = which ? wD : wA;
    __half* W = g_wc + (size_t)which * HH * 3072;
    const float* p = w + ((size_t)o * HH + h) * 3;
#pragma unroll
    for (int d = 0; d < 3; d++)
        W[(size_t)o * 3072 + d * 1024 + h] = __float2half_rn(p[d]);
}

__global__ void prep_out_w(const float* __restrict__ w) {
    int idx = blockIdx.x * 256 + threadIdx.x;  // 0..1M-1
    g_wo[idx] = __float2half_rn(w[idx]);
}

// zero padding rows (padrow 0 and 1025 of each batch)
__global__ void zero_pad_kernel() {
    int b = blockIdx.x >> 1;
    int top = blockIdx.x & 1;
    size_t off = ((size_t)b * MP + (top ? 1025 : 0)) * HH + threadIdx.x * 4;
    uint2 z = make_uint2(0u, 0u);
    *(uint2*)(g_ca + off) = z;
    *(uint2*)(g_cd + off) = z;
}

// ---------------- DWT -> fp16 (padded rows) ----------------
__global__ void dwt_kernel(const float* __restrict__ x) {
    int bm = blockIdx.x;
    int b = bm >> 10, m = bm & 1023;
    int h = threadIdx.x << 2;
    int s0 = 2 * m - 2, s1 = 2 * m - 1;
    if (s0 < 0) s0 = -s0 - 1;
    if (s1 < 0) s1 = -s1 - 1;
    const float* xb = x + (size_t)b * SS * HH + h;
    float4 v0 = *(const float4*)(xb + (size_t)s0 * HH);
    float4 v1 = *(const float4*)(xb + (size_t)s1 * HH);
    float4 v2 = *(const float4*)(xb + (size_t)(2 * m) * HH);
    float4 v3 = *(const float4*)(xb + (size_t)(2 * m + 1) * HH);
    __half ca[4], cd[4];
    ca[0] = __float2half_rn(C_H0 * v0.x + C_H1 * v1.x + C_H2 * v2.x + C_H3 * v3.x);
    ca[1] = __float2half_rn(C_H0 * v0.y + C_H1 * v1.y + C_H2 * v2.y + C_H3 * v3.y);
    ca[2] = __float2half_rn(C_H0 * v0.z + C_H1 * v1.z + C_H2 * v2.z + C_H3 * v3.z);
    ca[3] = __float2half_rn(C_H0 * v0.w + C_H1 * v1.w + C_H2 * v2.w + C_H3 * v3.w);
    cd[0] = __float2half_rn(C_H3 * v0.x - C_H2 * v1.x + C_H1 * v2.x - C_H0 * v3.x);
    cd[1] = __float2half_rn(C_H3 * v0.y - C_H2 * v1.y + C_H1 * v2.y - C_H0 * v3.y);
    cd[2] = __float2half_rn(C_H3 * v0.z - C_H2 * v1.z + C_H1 * v2.z - C_H0 * v3.z);
    cd[3] = __float2half_rn(C_H3 * v0.w - C_H2 * v1.w + C_H1 * v2.w - C_H0 * v3.w);
    size_t off = ((size_t)b * MP + m + 1) * HH + h;
    *(uint2*)(g_ca + off) = *(const uint2*)ca;
    *(uint2*)(g_cd + off) = *(const uint2*)cd;
}

// ---------------- iDWT: fp32 pa/pd -> fp16 recon ----------------
__global__ void idwt_kernel() {
    int bn = blockIdx.x;
    int b = bn >> 11, n = bn & 2047;
    int h = threadIdx.x << 2;
    size_t outoff = ((size_t)b * SS + n) * HH + h;
    if (n >= 2046) {
        *(uint2*)(g_rec + outoff) = make_uint2(0u, 0u);
        return;
    }
    int m0, m1;
    float wa0, wa1, wd0, wd1;
    if (!(n & 1)) {
        m0 = n >> 1; m1 = m0 + 1;
        wa1 = C_H0; wa0 = C_H2; wd1 = C_H3; wd0 = C_H1;
    } else {
        m0 = (n - 1) >> 1; m1 = m0 + 1;
        wa1 = C_H1; wa0 = C_H3; wd1 = -C_H2; wd0 = -C_H0;
    }
    size_t base = (size_t)b * MM * HH + h;
    float4 pa0 = *(const float4*)(g_pa + base + (size_t)m0 * HH);
    float4 pa1 = *(const float4*)(g_pa + base + (size_t)m1 * HH);
    float4 pd0 = *(const float4*)(g_pd + base + (size_t)m0 * HH);
    float4 pd1 = *(const float4*)(g_pd + base + (size_t)m1 * HH);
    __half rv[4];
    rv[0] = __float2half_rn(wa0 * pa0.x + wa1 * pa1.x + wd0 * pd0.x + wd1 * pd1.x);
    rv[1] = __float2half_rn(wa0 * pa0.y + wa1 * pa1.y + wd0 * pd0.y + wd1 * pd1.y);
    rv[2] = __float2half_rn(wa0 * pa0.z + wa1 * pa1.z + wd0 * pd0.z + wd1 * pd1.z);
    rv[3] = __float2half_rn(wa0 * pa0.w + wa1 * pa1.w + wd0 * pd0.w + wd1 * pd1.w);
    *(uint2*)(g_rec + outoff) = *(const uint2*)rv;
}

// ---------------------------------------------------------------------------
// fp16 GEMM body, TMA-fed: C[M,1024] = A[M,K] * B[1024,K]^T (+bias, opt GELU)
// Stages: 3 x (A 16KB + B 16KB), SW128 swizzled by TMA, BK=64.
// ---------------------------------------------------------------------------
template <bool CONV, bool GELU>
__device__ __forceinline__ void gemm_body(
    const CUtensorMap* __restrict__ tmA, const CUtensorMap* __restrict__ tmB,
    const float* __restrict__ bias, float* __restrict__ C,
    int kChunks, char* smem) {

    const uint32_t sbase = smem_u32(smem);
    const uint32_t mbars = sbase + 3 * STAGEB;

    const int tid = threadIdx.x;
    const int lane = tid & 31;
    const int wid = tid >> 5;
    const int row0 = blockIdx.y << 7;
    const int col0 = blockIdx.x << 7;
    const int arowBase = CONV ? ((row0 >> 10) * MP + (row0 & 1023)) : row0;

    if (tid == 0) {
        mbar_init(mbars + 0, 1);
        mbar_init(mbars + 8, 1);
        mbar_init(mbars + 16, 1);
    }
    __syncthreads();

    // prologue: stages 0,1
    if (tid == 0) {
#pragma unroll
        for (int c = 0; c < 2; c++) {
            const int k0 = c * BK;
            const uint32_t mb = mbars + c * 8;
            mbar_expect(mb, 2 * TILEB);
            const int ax = CONV ? (k0 & 1023) : k0;
            const int ay = CONV ? (arowBase + (k0 >> 10)) : arowBase;
            tma2d(sbase + c * STAGEB, tmA, ax, ay, mb);
            tma2d(sbase + c * STAGEB + TILEB, tmB, k0, col0, mb);
        }
    }

    // ldmatrix lane bases (logical offsets; swizzle applied per use)
    const int wm = (wid >> 2) * 64;       // warp m offset
    const int wn = (wid & 3) * 32;        // warp n offset
    const uint32_t aBase = (uint32_t)((wm + (lane & 15)) * 128 + ((lane >> 4) << 4));
    const uint32_t bBase = (uint32_t)((wn + (lane & 7) + ((lane >> 4) << 3)) * 128 +
                                      (((lane >> 3) & 1) << 4));

    float acc[4][4][4];
#pragma unroll
    for (int i = 0; i < 4; i++)
#pragma unroll
        for (int j = 0; j < 4; j++)
#pragma unroll
            for (int e = 0; e < 4; e++) acc[i][j][e] = 0.0f;

    for (int c = 0; c < kChunks; c++) {
        __syncthreads();   // all warps done with chunk c-1 -> stage (c+2)%3 reusable

        if (tid == 0 && c + 2 < kChunks) {
            const int c2 = c + 2;
            const int s2 = c2 % 3;
            const int k0 = c2 * BK;
            const uint32_t mb = mbars + s2 * 8;
            mbar_expect(mb, 2 * TILEB);
            const int ax = CONV ? (k0 & 1023) : k0;
            const int ay = CONV ? (arowBase + (k0 >> 10)) : arowBase;
            tma2d(sbase + s2 * STAGEB, tmA, ax, ay, mb);
            tma2d(sbase + s2 * STAGEB + TILEB, tmB, k0, col0, mb);
        }

        const int s = c % 3;
        mbar_wait(mbars + s * 8, (uint32_t)((c / 3) & 1));

        const uint32_t stA = sbase + s * STAGEB;
        const uint32_t stB = stA + TILEB;
#pragma unroll
        for (int kk = 0; kk < 4; kk++) {
            uint32_t af[4][4];
#pragma unroll
            for (int mt = 0; mt < 4; mt++) {
                const uint32_t lo = aBase + mt * (16 * 128) + kk * 32;
                ldm_x4(af[mt][0], af[mt][1], af[mt][2], af[mt][3], stA + sw128(lo));
            }
            uint32_t bf[4][2];
#pragma unroll
            for (int nt2 = 0; nt2 < 2; nt2++) {
                const uint32_t lo = bBase + nt2 * (16 * 128) + kk * 32;
                ldm_x4(bf[2 * nt2][0], bf[2 * nt2][1], bf[2 * nt2 + 1][0], bf[2 * nt2 + 1][1],
                       stB + sw128(lo));
            }
#pragma unroll
            for (int mt = 0; mt < 4; mt++)
#pragma unroll
                for (int nt = 0; nt < 4; nt++)
                    mma16816(acc[mt][nt], af[mt], bf[nt]);
        }
    }

    // ---- epilogue
    const int g = lane >> 2, t4 = lane & 3;
#pragma unroll
    for (int mt = 0; mt < 4; mt++) {
        const int m = row0 + wm + mt * 16 + g;
        float* crow0 = C + (size_t)m * HH;
        float* crow1 = crow0 + 8 * HH;
#pragma unroll
        for (int nt = 0; nt < 4; nt++) {
            const int n = col0 + wn + nt * 8 + 2 * t4;
            const float b0 = bias[n], b1 = bias[n + 1];
            float v0 = acc[mt][nt][0] + b0;
            float v1 = acc[mt][nt][1] + b1;
            float v2 = acc[mt][nt][2] + b0;
            float v3 = acc[mt][nt][3] + b1;
            if (GELU) {
                v0 = gelu_exact(v0); v1 = gelu_exact(v1);
                v2 = gelu_exact(v2); v3 = gelu_exact(v3);
            }
            *(float2*)(crow0 + n) = make_float2(v0, v1);
            *(float2*)(crow1 + n) = make_float2(v2, v3);
        }
    }
}

// conv GEMMs merged: grid.z selects approx (0) / detail (1)
__global__ __launch_bounds__(256, 2)
void conv_gemm(const __grid_constant__ CUtensorMap tmAca,
               const __grid_constant__ CUtensorMap tmAcd,
               const __grid_constant__ CUtensorMap tmBa,
               const __grid_constant__ CUtensorMap tmBd,
               const float* __restrict__ bias_a, const float* __restrict__ bias_d) {
    extern __shared__ __align__(1024) char smem[];
    const int which = blockIdx.z;
    const CUtensorMap* tA = which ? &tmAcd : &tmAca;
    const CUtensorMap* tB = which ? &tmBd : &tmBa;
    const float* bias = which ? bias_d : bias_a;
    float* C = which ? g_pd : g_pa;
    gemm_body<true, true>(tA, tB, bias, C, 48, smem);
}

__global__ __launch_bounds__(256, 2)
void out_gemm(const __grid_constant__ CUtensorMap tmA,
              const __grid_constant__ CUtensorMap tmB,
              const float* __restrict__ b_out, float* __restrict__ out) {
    extern __shared__ __align__(1024) char smem[];
    gemm_body<false, false>(&tmA, &tmB, b_out, out, 16, smem);
}

// ---------------------------------------------------------------------------
typedef CUresult (*PFN_encode)(
    CUtensorMap*, CUtensorMapDataType, cuuint32_t, void*,
    const cuuint64_t*, const cuuint64_t*, const cuuint32_t*, const cuuint32_t*,
    CUtensorMapInterleave, CUtensorMapSwizzle, CUtensorMapL2promotion,
    CUtensorMapFloatOOBfill);

static void enc2d(PFN_encode enc, CUtensorMap* tm, void* base,
                  unsigned long long inner, unsigned long long rows) {
    cuuint64_t dims[2] = {inner, rows};
    cuuint64_t strides[1] = {inner * 2};
    cuuint32_t box[2] = {64, 128};
    cuuint32_t es[2] = {1, 1};
    enc(tm, CU_TENSOR_MAP_DATA_TYPE_UINT16, 2, base, dims, strides, box, es,
        CU_TENSOR_MAP_INTERLEAVE_NONE, CU_TENSOR_MAP_SWIZZLE_128B,
        CU_TENSOR_MAP_L2_PROMOTION_L2_128B, CU_TENSOR_MAP_FLOAT_OOB_FILL_NONE);
}

extern "C" void kernel_launch(void* const* d_in, const int* in_sizes, int n_in,
                              void* d_out, int out_size) {
    const float* x        = (const float*)d_in[0];
    const float* w_approx = (const float*)d_in[1];
    const float* b_approx = (const float*)d_in[2];
    const float* w_detail = (const float*)d_in[3];
    const float* b_detail = (const float*)d_in[4];
    const float* w_out    = (const float*)d_in[5];
    const float* b_out    = (const float*)d_in[6];
    float* out = (float*)d_out;

    cudaFuncSetAttribute(conv_gemm, cudaFuncAttributeMaxDynamicSharedMemorySize, SMEM_BYTES);
    cudaFuncSetAttribute(out_gemm, cudaFuncAttributeMaxDynamicSharedMemorySize, SMEM_BYTES);

    void *p_ca, *p_cd, *p_rec, *p_wc, *p_wo;
    cudaGetSymbolAddress(&p_ca, g_ca);
    cudaGetSymbolAddress(&p_cd, g_cd);
    cudaGetSymbolAddress(&p_rec, g_rec);
    cudaGetSymbolAddress(&p_wc, g_wc);
    cudaGetSymbolAddress(&p_wo, g_wo);

    void* fn = nullptr;
    cudaDriverEntryPointQueryResult qr;
    cudaGetDriverEntryPoint("cuTensorMapEncodeTiled", &fn, cudaEnableDefault, &qr);
    PFN_encode enc = (PFN_encode)fn;

    CUtensorMap tmAca, tmAcd, tmBa, tmBd, tmArec, tmBo;
    enc2d(enc, &tmAca, p_ca, 1024, (unsigned long long)NB * MP);
    enc2d(enc, &tmAcd, p_cd, 1024, (unsigned long long)NB * MP);
    enc2d(enc, &tmBa, p_wc, 3072, 1024);
    enc2d(enc, &tmBd, (char*)p_wc + (size_t)HH * 3072 * 2, 3072, 1024);
    enc2d(enc, &tmArec, p_rec, 1024, (unsigned long long)NB * SS);
    enc2d(enc, &tmBo, p_wo, 1024, 1024);

    prep_conv_w<<<8192, 256>>>(w_approx, w_detail);
    prep_out_w<<<4096, 256>>>(w_out);
    zero_pad_kernel<<<16, 256>>>();
    dwt_kernel<<<NB * MM, 256>>>(x);

    // conv GEMMs: M=8192, N=1024, K=3072, both halves in one launch
    conv_gemm<<<dim3(8, 64, 2), 256, SMEM_BYTES>>>(tmAca, tmAcd, tmBa, tmBd,
                                                   b_approx, b_detail);

    idwt_kernel<<<NB * SS, 256>>>();

    // out GEMM: M=16384, N=1024, K=1024
    out_gemm<<<dim3(8, 128), 256, SMEM_BYTES>>>(tmArec, tmBo, b_out, out);
}